// round 10
// baseline (speedup 1.0000x reference)
#include <cuda_runtime.h>
#include <math.h>
#include <stdint.h>

#define BATCH 8192
#define NMAX  16
#define TSTEPS 4
#define DIN   4
#define DEMB  64
#define HID   128
#define G4    512
#define NSEQ  (BATCH*(1+NMAX))     // 139264 sequences
#define MTILE 64                   // sequences per tile
#define LGRID 1024                 // lstm grid (tile-stride loop)

// ---------------- scratch (device globals: allocation-free) ----------------
__device__ float    g_H[(size_t)NSEQ*HID];      // final hidden; masked entries stay 0
__device__ uint32_t g_Wbf[12*2*512*8];          // weights bf16 hi/lo, permuted
__device__ float    g_bsum[G4];
__device__ int      g_cnt;                      // number of active sequences
__device__ int      g_active[NSEQ];             // compacted active ids

// ---------------- smem layout (4-byte words) ----------------
// A: 12 chunks x 2 parts x 64 rows x 8 words = 12288
// B: 3 bufs x 8192                            = 24576
// C: [64][132] floats                          = 8448
// bias 512 | We 256 | be 64
#define A_OFF  0
#define B_OFF  12288
#define C_OFF  36864
#define BS_OFF 45312
#define WE_OFF 45824
#define BE_OFF 46080
#define SMEM_WORDS 46144
#define SMEM_BYTES (SMEM_WORDS*4)   // 184576

__device__ __forceinline__ void cp16(void* sdst, const void* gsrc) {
    uint32_t sa = (uint32_t)__cvta_generic_to_shared(sdst);
    asm volatile("cp.async.cg.shared.global [%0], [%1], 16;" :: "r"(sa), "l"(gsrc));
}
#define CP_COMMIT() asm volatile("cp.async.commit_group;" ::: "memory")
#define CP_WAIT(N)  asm volatile("cp.async.wait_group %0;" :: "n"(N) : "memory")

__device__ __forceinline__ uint32_t pack_bf2(float v0, float v1) {
    uint32_t r;
    asm("cvt.rn.bf16x2.f32 %0, %1, %2;" : "=r"(r) : "f"(v1), "f"(v0));
    return r;
}
__device__ __forceinline__ void split2(float v0, float v1, uint32_t& h, uint32_t& l) {
    h = pack_bf2(v0, v1);
    float r0 = v0 - __uint_as_float(h << 16);
    float r1 = v1 - __uint_as_float(h & 0xFFFF0000u);
    l = pack_bf2(r0, r1);
}

#define MMA_BF16(D, A0,A1,A2,A3, B0,B1)                                        \
    asm volatile(                                                              \
        "mma.sync.aligned.m16n8k16.row.col.f32.bf16.bf16.f32 "                 \
        "{%0,%1,%2,%3},{%4,%5,%6,%7},{%8,%9},{%0,%1,%2,%3};"                   \
        : "+f"((D)[0]), "+f"((D)[1]), "+f"((D)[2]), "+f"((D)[3])               \
        : "r"(A0), "r"(A1), "r"(A2), "r"(A3), "r"(B0), "r"(B1))

// ---------------- prep: split weights; also resets g_cnt ----------------
__global__ void prep_kernel(const float* __restrict__ Wih, const float* __restrict__ Whh,
                            const float* __restrict__ bih, const float* __restrict__ bhh) {
    int i = blockIdx.x * 256 + threadIdx.x;
    if (i == 0) g_cnt = 0;
    if (i < 12 * 512 * 8) {
        int w = i & 7, n = (i >> 3) & 511, c = i >> 12;
        int pp = (w & 1) ? 4 + (w >> 1) : (w >> 1);
        int k = c * 16 + 2 * pp;
        float v0, v1;
        if (k < DEMB) { v0 = Wih[n * DEMB + k];        v1 = Wih[n * DEMB + k + 1]; }
        else          { v0 = Whh[n * HID + (k - 64)];  v1 = Whh[n * HID + (k - 63)]; }
        uint32_t h, l;
        split2(v0, v1, h, l);
        g_Wbf[(c * 2 + 0) * 4096 + n * 8 + w] = h;
        g_Wbf[(c * 2 + 1) * 4096 + n * 8 + w] = l;
    }
    if (i < G4) g_bsum[i] = bih[i] + bhh[i];
}

// ---------------- compaction: active = targets + unmasked neighbors ----------------
__global__ void append_kernel(const int* __restrict__ mask) {
    int i = blockIdx.x * 256 + threadIdx.x;
    bool act = false;
    if (i < NSEQ) act = (i < BATCH) || (mask[i - BATCH] != 0);
    unsigned bal = __ballot_sync(0xFFFFFFFFu, act);
    int lane = threadIdx.x & 31;
    int n = __popc(bal);
    int base = 0;
    if (lane == 0 && n) base = atomicAdd(&g_cnt, n);
    base = __shfl_sync(0xFFFFFFFFu, base, 0);
    if (act) g_active[base + __popc(bal & ((1u << lane) - 1))] = i;
}

// ---------------- persistent 3xBF16 LSTM: 3-buf B pipeline, 1 sync/chunk ----------------
__global__ void __launch_bounds__(512, 1)
lstm_fused_kernel(const float* __restrict__ x, const float* __restrict__ nb,
                  const float* __restrict__ We, const float* __restrict__ be) {
    extern __shared__ uint32_t smw[];
    uint32_t* Asw = smw + A_OFF;
    uint32_t* Bsw = smw + B_OFF;
    float*    Cs  = (float*)(smw + C_OFF);
    float*    bs  = (float*)(smw + BS_OFF);
    float*    WeS = (float*)(smw + WE_OFF);
    float*    beS = (float*)(smw + BE_OFF);

    const int tid  = threadIdx.x;
    const int lane = tid & 31, wid = tid >> 5;
    const int wm = wid & 3, wn = wid >> 2;
    const int g = lane >> 2, q = lane & 3;
    const int m0 = wm * 16;
    const int cnt = g_cnt;

    bs[tid] = g_bsum[tid];
    if (tid < 256) WeS[tid] = We[tid];
    if (tid < 64)  beS[tid] = be[tid];

    auto load_B = [&](int c, int buf) {
#pragma unroll
        for (int i = 0; i < 4; i++) {
            int idx = tid + i * 512;
            cp16(Bsw + buf * 8192 + idx * 4, g_Wbf + c * 8192 + idx * 4);
        }
    };

    for (int tile = blockIdx.x; tile * MTILE < cnt; tile += LGRID) {
        const int row0 = tile * MTILE;
        const int rowi = row0 + (tid >> 3);
        const int id   = g_active[rowi < cnt ? rowi : cnt - 1];   // clamp partial tile

        // inline embed: E(t) -> A chunks 0..3 (bf16 hi/lo permuted); direct ST.shared
        auto compute_E = [&](int t) {
            const int row = tid >> 3, sub = tid & 7;
            const float* src = (id < BATCH)
                ? x  + ((size_t)id * TSTEPS + t) * DIN
                : nb + ((size_t)(id - BATCH) * TSTEPS + t) * DIN;
            float4 xv = *(const float4*)src;
#pragma unroll
            for (int ch = 0; ch < 4; ch++) {
                const int w  = sub;
                const int pp = (w & 1) ? 4 + (w >> 1) : (w >> 1);
                const int j  = ch * 16 + 2 * pp;
                float v0 = beS[j], v1 = beS[j + 1];
                v0 = fmaf(xv.x, WeS[j*4+0], v0); v0 = fmaf(xv.y, WeS[j*4+1], v0);
                v0 = fmaf(xv.z, WeS[j*4+2], v0); v0 = fmaf(xv.w, WeS[j*4+3], v0);
                v1 = fmaf(xv.x, WeS[(j+1)*4+0], v1); v1 = fmaf(xv.y, WeS[(j+1)*4+1], v1);
                v1 = fmaf(xv.z, WeS[(j+1)*4+2], v1); v1 = fmaf(xv.w, WeS[(j+1)*4+3], v1);
                v0 = fmaxf(v0, 0.f); v1 = fmaxf(v1, 0.f);
                uint32_t h, l;
                split2(v0, v1, h, l);
                Asw[(ch * 2 + 0) * 512 + row * 8 + w] = h;
                Asw[(ch * 2 + 1) * 512 + row * 8 + w] = l;
            }
        };

        // prologue: global B positions 0,1 into bufs 0,1; E(0)
        load_B(0, 0); CP_COMMIT();
        load_B(1, 1); CP_COMMIT();
        compute_E(0);

        for (int t = 0; t < TSTEPS; t++) {
            const int nch = (t == 0) ? 4 : 12;
            float acc[4][4][4];
#pragma unroll
            for (int a = 0; a < 4; a++)
#pragma unroll
                for (int b = 0; b < 4; b++)
#pragma unroll
                    for (int c = 0; c < 4; c++) acc[a][b][c] = 0.f;

            for (int c = 0; c < nch; c++) {
                const int p = (t == 0) ? c : 4 + (t - 1) * 12 + c;   // global B position
                if (t == 3 && c == 11) { CP_WAIT(0); } else { CP_WAIT(1); }
                __syncthreads();                                     // the ONLY per-chunk sync

                const uint32_t* Ach = Asw + (c * 2) * 512;
                uint2 ahA = *(const uint2*)(Ach + (m0 + g) * 8 + 2 * q);
                uint2 ahB = *(const uint2*)(Ach + (m0 + g + 8) * 8 + 2 * q);
                uint2 alA = *(const uint2*)(Ach + 512 + (m0 + g) * 8 + 2 * q);
                uint2 alB = *(const uint2*)(Ach + 512 + (m0 + g + 8) * 8 + 2 * q);
                const uint32_t* Bh = Bsw + (p % 3) * 8192;
                const uint32_t* Bl = Bh + 4096;
#pragma unroll
                for (int gate = 0; gate < 4; gate++)
#pragma unroll
                    for (int s = 0; s < 4; s++) {
                        int n = gate * 128 + wn * 32 + s * 8 + g;
                        uint2 bh = *(const uint2*)(Bh + n * 8 + 2 * q);
                        uint2 bl = *(const uint2*)(Bl + n * 8 + 2 * q);
                        float* d = acc[gate][s];
                        MMA_BF16(d, ahA.x, ahB.x, ahA.y, ahB.y, bh.x, bh.y);
                        MMA_BF16(d, alA.x, alB.x, alA.y, alB.y, bh.x, bh.y);
                        MMA_BF16(d, ahA.x, ahB.x, ahA.y, ahB.y, bl.x, bl.y);
                    }

                // prefetch global position p+2 (buf (p+2)%3; last read at p-1, safe)
                if (!(t == 3 && c >= 10)) {
                    int pn = p + 2;
                    load_B(pn < 4 ? pn : (pn - 4) % 12, pn % 3); CP_COMMIT();
                }
                // E(t+1) overlapped at t=1,2 (E chunks 0-3 idle since chunk 3)
                if (t >= 1 && t < 3 && c == nch - 2) compute_E(t + 1);
            }

            __syncthreads();          // pre-epilogue: all MMA reads of A/B done
            if (t == 0) compute_E(1); // E chunks 0-3 free now (chunk 3 reads done)

            // ---- register epilogue: gates -> c,h; h split to bf16 into A slots ----
#pragma unroll
            for (int s = 0; s < 4; s++)
#pragma unroll
                for (int h2 = 0; h2 < 2; h2++) {
                    const int rl = m0 + g + h2 * 8;
                    const int j0 = wn * 32 + s * 8 + 2 * q;
                    float hh[2];
#pragma unroll
                    for (int e = 0; e < 2; e++) {
                        const int j  = j0 + e;
                        const int ci = h2 * 2 + e;
                        float pi = acc[0][s][ci] + bs[j];
                        float pf = acc[1][s][ci] + bs[128 + j];
                        float pg = acc[2][s][ci] + bs[256 + j];
                        float po = acc[3][s][ci] + bs[384 + j];
                        float iv = 1.f / (1.f + expf(-pi));
                        float fv = 1.f / (1.f + expf(-pf));
                        float gv = tanhf(pg);
                        float ov = 1.f / (1.f + expf(-po));
                        float cp = (t == 0) ? 0.f : Cs[rl * 132 + j];
                        float cc = fmaf(fv, cp, iv * gv);
                        Cs[rl * 132 + j] = cc;
                        hh[e] = ov * tanhf(cc);
                    }
                    if (t < 3) {
                        const int ch = 4 + (j0 >> 4);
                        const int lp = (j0 & 15) >> 1;
                        const int w  = (lp < 4) ? 2 * lp : 2 * (lp - 4) + 1;
                        uint32_t h, l;
                        split2(hh[0], hh[1], h, l);
                        Asw[(ch * 2 + 0) * 512 + rl * 8 + w] = h;
                        Asw[(ch * 2 + 1) * 512 + rl * 8 + w] = l;
                    } else {
                        float* stage = (float*)Bsw;     // B bufs dead after t=3 chunks
                        stage[rl * 132 + j0]     = hh[0];
                        stage[rl * 132 + j0 + 1] = hh[1];
                    }
                }

            if (t == 3) {
                __syncthreads();
                const float* stage = (const float*)Bsw;
                const int r = tid >> 3, j0 = (tid & 7) * 16;
                const size_t hb = (size_t)id * HID;
#pragma unroll
                for (int v = 0; v < 4; v++) {
                    float4 val = *(const float4*)&stage[r * 132 + j0 + v * 4];
                    *(float4*)&g_H[hb + j0 + v * 4] = val;
                }
            }
        }
        __syncthreads();   // stage reads done before next tile's load_B overwrites Bsw
    }
}

// ---------------- head: 8 rows/block, masked loads skipped ----------------
#define H_HF   0
#define H_HID  2048
#define H_LG   3072
#define H_SMEM_FLOATS 3104
#define H_SMEM_BYTES (H_SMEM_FLOATS*4)

__global__ void __launch_bounds__(256) head_kernel(
        const int* __restrict__ mask,
        const float* __restrict__ W1, const float* __restrict__ b1,
        const float* __restrict__ W2, const float* __restrict__ b2,
        const float* __restrict__ Wp, const float* __restrict__ bp,
        float* __restrict__ out) {
    extern __shared__ float hs[];
    float* hf  = hs + H_HF;    // [8][256]
    float* hid = hs + H_HID;   // [8][128]
    float* lg  = hs + H_LG;    // [8][4]

    const int tid = threadIdx.x;
    const int j   = tid & 127, rh = tid >> 7;
    const int b0  = blockIdx.x * 8;

#pragma unroll
    for (int r4 = 0; r4 < 4; r4++) {
        int r = rh * 4 + r4, b = b0 + r;
        hf[r * 256 + j] = g_H[(size_t)b * HID + j];
        float s = 0.f, cnt = 0.f;
#pragma unroll
        for (int n = 0; n < NMAX; n++) {
            if (mask[b * NMAX + n] != 0) {
                s += g_H[(size_t)(BATCH + b * NMAX + n) * HID + j];
                cnt += 1.f;
            }
        }
        hf[r * 256 + 128 + j] = s / fmaxf(cnt, 1.f);
    }
    __syncthreads();

    {
        float acc[4];
        float bj = b1[j];
#pragma unroll
        for (int r = 0; r < 4; r++) acc[r] = bj;
        for (int k4 = 0; k4 < 64; k4++) {
            float4 w = *(const float4*)&W1[(size_t)j * 256 + k4 * 4];
#pragma unroll
            for (int r4 = 0; r4 < 4; r4++) {
                float4 h4 = *(const float4*)&hf[(rh * 4 + r4) * 256 + k4 * 4];
                acc[r4] = fmaf(w.x, h4.x, fmaf(w.y, h4.y, fmaf(w.z, h4.z, fmaf(w.w, h4.w, acc[r4]))));
            }
        }
#pragma unroll
        for (int r4 = 0; r4 < 4; r4++)
            hid[(rh * 4 + r4) * 128 + j] = fmaxf(acc[r4], 0.f);
    }
    __syncthreads();

    for (int idx = tid; idx < 8 * 36; idx += 256) {
        int r = idx / 36, o = idx % 36;
        float a = b2[o];
        for (int k4 = 0; k4 < 32; k4++) {
            float4 w  = *(const float4*)&W2[(size_t)o * 128 + k4 * 4];
            float4 h4 = *(const float4*)&hid[r * 128 + k4 * 4];
            a = fmaf(w.x, h4.x, fmaf(w.y, h4.y, fmaf(w.z, h4.z, fmaf(w.w, h4.w, a))));
        }
        out[(size_t)(b0 + r) * 36 + o] = a;
    }
    if (tid < 24) {
        int r = tid / 3, kk = tid % 3;
        float a = bp[kk];
        for (int k4 = 0; k4 < 64; k4++) {
            float4 w  = *(const float4*)&Wp[(size_t)kk * 256 + k4 * 4];
            float4 h4 = *(const float4*)&hf[r * 256 + k4 * 4];
            a = fmaf(w.x, h4.x, fmaf(w.y, h4.y, fmaf(w.z, h4.z, fmaf(w.w, h4.w, a))));
        }
        lg[r * 4 + kk] = a;
    }
    __syncthreads();
    if (tid < 24) {
        int r = tid / 3, kk = tid % 3;
        float m  = fmaxf(lg[r * 4], fmaxf(lg[r * 4 + 1], lg[r * 4 + 2]));
        float e0 = expf(lg[r * 4] - m), e1 = expf(lg[r * 4 + 1] - m), e2 = expf(lg[r * 4 + 2] - m);
        float e  = (kk == 0) ? e0 : ((kk == 1) ? e1 : e2);
        out[(size_t)BATCH * 36 + (size_t)(b0 + r) * 3 + kk] = e / (e0 + e1 + e2);
    }
}

// ---------------- launch ----------------
extern "C" void kernel_launch(void* const* d_in, const int* in_sizes, int n_in,
                              void* d_out, int out_size) {
    const float* x    = (const float*)d_in[0];
    const float* nb   = (const float*)d_in[1];
    const int*   mask = (const int*)  d_in[2];
    const float* We   = (const float*)d_in[3];
    const float* be   = (const float*)d_in[4];
    const float* Wih  = (const float*)d_in[5];
    const float* Whh  = (const float*)d_in[6];
    const float* bih  = (const float*)d_in[7];
    const float* bhh  = (const float*)d_in[8];
    const float* W1   = (const float*)d_in[9];
    const float* b1   = (const float*)d_in[10];
    const float* W2   = (const float*)d_in[11];
    const float* b2   = (const float*)d_in[12];
    const float* Wp   = (const float*)d_in[13];
    const float* bp   = (const float*)d_in[14];
    float* out = (float*)d_out;

    cudaFuncSetAttribute(lstm_fused_kernel, cudaFuncAttributeMaxDynamicSharedMemorySize, SMEM_BYTES);
    cudaFuncSetAttribute(head_kernel, cudaFuncAttributeMaxDynamicSharedMemorySize, H_SMEM_BYTES);

    prep_kernel<<<(12 * 512 * 8 + 255) / 256, 256>>>(Wih, Whh, bih, bhh);
    append_kernel<<<(NSEQ + 255) / 256, 256>>>(mask);

    lstm_fused_kernel<<<LGRID, 512, SMEM_BYTES>>>(x, nb, We, be);

    head_kernel<<<BATCH / 8, 256, H_SMEM_BYTES>>>(mask, W1, b1, W2, b2, Wp, bp, out);
}

// round 12
// speedup vs baseline: 1.1227x; 1.1227x over previous
#include <cuda_runtime.h>
#include <math.h>
#include <stdint.h>

#define BATCH 8192
#define NMAX  16
#define TSTEPS 4
#define DIN   4
#define DEMB  64
#define HID   128
#define G4    512
#define NSEQ  (BATCH*(1+NMAX))     // 139264 sequences
#define MTILE 64                   // sequences per CTA

// ---------------- scratch (device globals: allocation-free) ----------------
__device__ float    g_H[(size_t)NSEQ*HID];      // final hidden; masked entries stay 0
__device__ uint32_t g_Wbf[12*2*512*8];          // weights bf16 hi/lo, permuted
__device__ float    g_bsum[G4];
__device__ int      g_cnt;                      // number of active sequences
__device__ int      g_active[NSEQ];             // compacted active ids (padded with 0)

// ---------------- smem layout (4-byte words) — round-9 verbatim ----------------
#define A_OFF  0
#define B_OFF  12288
#define C_OFF  28672
#define BS_OFF 37120
#define WE_OFF 37632
#define BE_OFF 37888
#define ID_OFF 37952
#define SMEM_WORDS 38016
#define SMEM_BYTES (SMEM_WORDS*4)   // 152064

__device__ __forceinline__ void cp16(void* sdst, const void* gsrc) {
    uint32_t sa = (uint32_t)__cvta_generic_to_shared(sdst);
    asm volatile("cp.async.cg.shared.global [%0], [%1], 16;" :: "r"(sa), "l"(gsrc));
}
#define CP_COMMIT() asm volatile("cp.async.commit_group;" ::: "memory")
#define CP_WAIT(N)  asm volatile("cp.async.wait_group %0;" :: "n"(N) : "memory")

__device__ __forceinline__ uint32_t pack_bf2(float v0, float v1) {
    uint32_t r;
    asm("cvt.rn.bf16x2.f32 %0, %1, %2;" : "=r"(r) : "f"(v1), "f"(v0));
    return r;
}
__device__ __forceinline__ void split2(float v0, float v1, uint32_t& h, uint32_t& l) {
    h = pack_bf2(v0, v1);
    float r0 = v0 - __uint_as_float(h << 16);
    float r1 = v1 - __uint_as_float(h & 0xFFFF0000u);
    l = pack_bf2(r0, r1);
}

#define MMA_BF16(D, A0,A1,A2,A3, B0,B1)                                        \
    asm volatile(                                                              \
        "mma.sync.aligned.m16n8k16.row.col.f32.bf16.bf16.f32 "                 \
        "{%0,%1,%2,%3},{%4,%5,%6,%7},{%8,%9},{%0,%1,%2,%3};"                   \
        : "+f"((D)[0]), "+f"((D)[1]), "+f"((D)[2]), "+f"((D)[3])               \
        : "r"(A0), "r"(A1), "r"(A2), "r"(A3), "r"(B0), "r"(B1))

// ---------------- prep: split weights; resets g_cnt ----------------
__global__ void prep_kernel(const float* __restrict__ Wih, const float* __restrict__ Whh,
                            const float* __restrict__ bih, const float* __restrict__ bhh) {
    int i = blockIdx.x * 256 + threadIdx.x;
    if (i == 0) g_cnt = 0;
    if (i < 12 * 512 * 8) {
        int w = i & 7, n = (i >> 3) & 511, c = i >> 12;
        int pp = (w & 1) ? 4 + (w >> 1) : (w >> 1);
        int k = c * 16 + 2 * pp;
        float v0, v1;
        if (k < DEMB) { v0 = Wih[n * DEMB + k];        v1 = Wih[n * DEMB + k + 1]; }
        else          { v0 = Whh[n * HID + (k - 64)];  v1 = Whh[n * HID + (k - 63)]; }
        uint32_t h, l;
        split2(v0, v1, h, l);
        g_Wbf[(c * 2 + 0) * 4096 + n * 8 + w] = h;
        g_Wbf[(c * 2 + 1) * 4096 + n * 8 + w] = l;
    }
    if (i < G4) g_bsum[i] = bih[i] + bhh[i];
}

// ---------------- compaction ----------------
__global__ void append_kernel(const int* __restrict__ mask) {
    int i = blockIdx.x * 256 + threadIdx.x;
    bool act = false;
    if (i < NSEQ) act = (i < BATCH) || (mask[i - BATCH] != 0);
    unsigned bal = __ballot_sync(0xFFFFFFFFu, act);
    int lane = threadIdx.x & 31;
    int n = __popc(bal);
    int base = 0;
    if (lane == 0 && n) base = atomicAdd(&g_cnt, n);
    base = __shfl_sync(0xFFFFFFFFu, base, 0);
    if (act) g_active[base + __popc(bal & ((1u << lane) - 1))] = i;
}

__global__ void pad_kernel() {
    int i = blockIdx.x * 256 + threadIdx.x;
    if (i < NSEQ && i >= g_cnt) g_active[i] = 0;   // duplicate seq 0: benign idempotent work
}

// ---------------- persistent 3xBF16 LSTM (round-9 pipeline, verbatim) ----------------
__global__ void __launch_bounds__(512, 1)
lstm_fused_kernel(const float* __restrict__ x, const float* __restrict__ nb,
                  const float* __restrict__ We, const float* __restrict__ be) {
    if (blockIdx.x * MTILE >= g_cnt) return;       // fully-inactive CTA

    extern __shared__ uint32_t smw[];
    uint32_t* Asw = smw + A_OFF;
    uint32_t* Bsw = smw + B_OFF;
    float*    Cs  = (float*)(smw + C_OFF);
    float*    bs  = (float*)(smw + BS_OFF);
    float*    WeS = (float*)(smw + WE_OFF);
    float*    beS = (float*)(smw + BE_OFF);
    int*      ids = (int*)  (smw + ID_OFF);

    const int tid  = threadIdx.x;
    const int lane = tid & 31, wid = tid >> 5;
    const int wm = wid & 3, wn = wid >> 2;
    const int g = lane >> 2, q = lane & 3;
    const int m0 = wm * 16;
    const int row0 = blockIdx.x * MTILE;

    bs[tid] = g_bsum[tid];
    if (tid < 256) WeS[tid] = We[tid];
    if (tid < 64)  { beS[tid] = be[tid]; ids[tid] = g_active[row0 + tid]; }
    __syncthreads();

    auto compute_E = [&](int t) {
        const int row = tid >> 3, sub = tid & 7;
        const int id  = ids[row];
        const float* src = (id < BATCH)
            ? x  + ((size_t)id * TSTEPS + t) * DIN
            : nb + ((size_t)(id - BATCH) * TSTEPS + t) * DIN;
        float4 xv = *(const float4*)src;
#pragma unroll
        for (int ch = 0; ch < 4; ch++) {
            const int w  = sub;
            const int pp = (w & 1) ? 4 + (w >> 1) : (w >> 1);
            const int j  = ch * 16 + 2 * pp;
            float v0 = beS[j], v1 = beS[j + 1];
            v0 = fmaf(xv.x, WeS[j*4+0], v0); v0 = fmaf(xv.y, WeS[j*4+1], v0);
            v0 = fmaf(xv.z, WeS[j*4+2], v0); v0 = fmaf(xv.w, WeS[j*4+3], v0);
            v1 = fmaf(xv.x, WeS[(j+1)*4+0], v1); v1 = fmaf(xv.y, WeS[(j+1)*4+1], v1);
            v1 = fmaf(xv.z, WeS[(j+1)*4+2], v1); v1 = fmaf(xv.w, WeS[(j+1)*4+3], v1);
            v0 = fmaxf(v0, 0.f); v1 = fmaxf(v1, 0.f);
            uint32_t h, l;
            split2(v0, v1, h, l);
            Asw[(ch * 2 + 0) * 512 + row * 8 + w] = h;
            Asw[(ch * 2 + 1) * 512 + row * 8 + w] = l;
        }
    };
    auto load_B = [&](int c, int buf) {
#pragma unroll
        for (int i = 0; i < 4; i++) {
            int idx = tid + i * 512;
            cp16(Bsw + buf * 8192 + idx * 4, g_Wbf + c * 8192 + idx * 4);
        }
    };

    compute_E(0);
    load_B(0, 0); CP_COMMIT();
    load_B(1, 1); CP_COMMIT();

    for (int t = 0; t < TSTEPS; t++) {
        const int nch = (t == 0) ? 4 : 12;
        float acc[4][4][4];
#pragma unroll
        for (int a = 0; a < 4; a++)
#pragma unroll
            for (int b = 0; b < 4; b++)
#pragma unroll
                for (int c = 0; c < 4; c++) acc[a][b][c] = 0.f;

        for (int c = 0; c < nch; c++) {
            if (c == nch - 1) { CP_WAIT(0); } else { CP_WAIT(1); }
            __syncthreads();

            const uint32_t* Ach = Asw + (c * 2) * 512;
            uint2 ahA = *(const uint2*)(Ach + (m0 + g) * 8 + 2 * q);
            uint2 ahB = *(const uint2*)(Ach + (m0 + g + 8) * 8 + 2 * q);
            uint2 alA = *(const uint2*)(Ach + 512 + (m0 + g) * 8 + 2 * q);
            uint2 alB = *(const uint2*)(Ach + 512 + (m0 + g + 8) * 8 + 2 * q);
            const uint32_t* Bh = Bsw + (c & 1) * 8192;
            const uint32_t* Bl = Bh + 4096;
#pragma unroll
            for (int gate = 0; gate < 4; gate++)
#pragma unroll
                for (int s = 0; s < 4; s++) {
                    int n = gate * 128 + wn * 32 + s * 8 + g;
                    uint2 bh = *(const uint2*)(Bh + n * 8 + 2 * q);
                    uint2 bl = *(const uint2*)(Bl + n * 8 + 2 * q);
                    float* d = acc[gate][s];
                    MMA_BF16(d, ahA.x, ahB.x, ahA.y, ahB.y, bh.x, bh.y);
                    MMA_BF16(d, alA.x, alB.x, alA.y, alB.y, bh.x, bh.y);
                    MMA_BF16(d, ahA.x, ahB.x, ahA.y, ahB.y, bl.x, bl.y);
                }
            __syncthreads();

            // ---- prefetch / E-compute schedule (race-free; validated rounds 6-9) ----
            if (c + 2 < nch)                          { load_B(c + 2, c & 1); CP_COMMIT(); }
            else if (c == nch - 2 && t >= 1 && t < 3) { compute_E(t + 1); }
            else if (c == nch - 1 && t < 3) {
                if (t == 0) compute_E(1);
                load_B(0, 0); CP_COMMIT();
                load_B(1, 1); CP_COMMIT();
            }
        }

        // ---- register epilogue: gates -> c,h; h split to bf16 into A slots ----
#pragma unroll
        for (int s = 0; s < 4; s++)
#pragma unroll
            for (int h2 = 0; h2 < 2; h2++) {
                const int rl = m0 + g + h2 * 8;
                const int j0 = wn * 32 + s * 8 + 2 * q;
                float hh[2];
#pragma unroll
                for (int e = 0; e < 2; e++) {
                    const int j  = j0 + e;
                    const int ci = h2 * 2 + e;
                    float pi = acc[0][s][ci] + bs[j];
                    float pf = acc[1][s][ci] + bs[128 + j];
                    float pg = acc[2][s][ci] + bs[256 + j];
                    float po = acc[3][s][ci] + bs[384 + j];
                    float iv = 1.f / (1.f + expf(-pi));
                    float fv = 1.f / (1.f + expf(-pf));
                    float gv = tanhf(pg);
                    float ov = 1.f / (1.f + expf(-po));
                    float cp = (t == 0) ? 0.f : Cs[rl * 132 + j];
                    float cc = fmaf(fv, cp, iv * gv);
                    Cs[rl * 132 + j] = cc;
                    hh[e] = ov * tanhf(cc);
                }
                if (t < 3) {
                    const int ch = 4 + (j0 >> 4);
                    const int lp = (j0 & 15) >> 1;
                    const int w  = (lp < 4) ? 2 * lp : 2 * (lp - 4) + 1;
                    uint32_t h, l;
                    split2(hh[0], hh[1], h, l);
                    Asw[(ch * 2 + 0) * 512 + rl * 8 + w] = h;
                    Asw[(ch * 2 + 1) * 512 + rl * 8 + w] = l;
                } else {
                    float* stage = (float*)Bsw;
                    stage[rl * 132 + j0]     = hh[0];
                    stage[rl * 132 + j0 + 1] = hh[1];
                }
            }

        if (t == 3) {
            __syncthreads();
            const float* stage = (const float*)Bsw;
            const int r = tid >> 3, j0 = (tid & 7) * 16;
            const size_t hb = (size_t)ids[r] * HID;
#pragma unroll
            for (int v = 0; v < 4; v++) {
                float4 val = *(const float4*)&stage[r * 132 + j0 + v * 4];
                *(float4*)&g_H[hb + j0 + v * 4] = val;
            }
        }
    }
}

// ---------------- head v5: 16 rows/block; pooling with per-thread 8-j slice (MLP~32) ----------------
#define H_HF   0
#define H_HID  4096
#define H_LG   6144
#define H_SMEM_FLOATS 6208
#define H_SMEM_BYTES (H_SMEM_FLOATS*4)

__global__ void __launch_bounds__(256) head_kernel(
        const int* __restrict__ mask,
        const float* __restrict__ W1, const float* __restrict__ b1,
        const float* __restrict__ W2, const float* __restrict__ b2,
        const float* __restrict__ Wp, const float* __restrict__ bp,
        float* __restrict__ out) {
    extern __shared__ float hs[];
    float* hf  = hs + H_HF;    // [16][256]
    float* hid = hs + H_HID;   // [16][128]
    float* lg  = hs + H_LG;    // [16][4]

    const int tid = threadIdx.x;
    const int b0  = blockIdx.x * 16;

    // ---- pooling: thread = (row r, 8-wide j slice). 34 independent float4 loads. ----
    {
        const int r  = tid >> 4;           // 0..15
        const int j0 = (tid & 15) * 8;     // 0..120
        const int b  = b0 + r;
        float4 t0 = *(const float4*)&g_H[(size_t)b * HID + j0];
        float4 t1 = *(const float4*)&g_H[(size_t)b * HID + j0 + 4];
        *(float4*)&hf[r * 256 + j0]     = t0;
        *(float4*)&hf[r * 256 + j0 + 4] = t1;

        float4 sa = make_float4(0.f, 0.f, 0.f, 0.f);
        float4 sb = make_float4(0.f, 0.f, 0.f, 0.f);
        float cnt = 0.f;
#pragma unroll
        for (int n = 0; n < NMAX; n++) {
            float m = (float)mask[b * NMAX + n];          // masked rows of g_H are 0
            const float* hp = &g_H[(size_t)(BATCH + b * NMAX + n) * HID + j0];
            float4 ha = *(const float4*)hp;
            float4 hb = *(const float4*)(hp + 4);
            sa.x = fmaf(m, ha.x, sa.x); sa.y = fmaf(m, ha.y, sa.y);
            sa.z = fmaf(m, ha.z, sa.z); sa.w = fmaf(m, ha.w, sa.w);
            sb.x = fmaf(m, hb.x, sb.x); sb.y = fmaf(m, hb.y, sb.y);
            sb.z = fmaf(m, hb.z, sb.z); sb.w = fmaf(m, hb.w, sb.w);
            cnt += m;
        }
        float cd = fmaxf(cnt, 1.f);
        hf[r * 256 + 128 + j0 + 0] = sa.x / cd;
        hf[r * 256 + 128 + j0 + 1] = sa.y / cd;
        hf[r * 256 + 128 + j0 + 2] = sa.z / cd;
        hf[r * 256 + 128 + j0 + 3] = sa.w / cd;
        hf[r * 256 + 128 + j0 + 4] = sb.x / cd;
        hf[r * 256 + 128 + j0 + 5] = sb.y / cd;
        hf[r * 256 + 128 + j0 + 6] = sb.z / cd;
        hf[r * 256 + 128 + j0 + 7] = sb.w / cd;
    }
    __syncthreads();

    // ---- MLP1 (round-8 verbatim): hidden = relu(hf @ W1^T + b1), 8 rows/thread ----
    {
        const int j = tid & 127, rh = tid >> 7;
        float acc[8];
        float bj = b1[j];
#pragma unroll
        for (int r = 0; r < 8; r++) acc[r] = bj;
        for (int k4 = 0; k4 < 64; k4++) {
            float4 w = *(const float4*)&W1[(size_t)j * 256 + k4 * 4];
#pragma unroll
            for (int r8 = 0; r8 < 8; r8++) {
                float4 h4 = *(const float4*)&hf[(rh * 8 + r8) * 256 + k4 * 4];
                acc[r8] = fmaf(w.x, h4.x, fmaf(w.y, h4.y, fmaf(w.z, h4.z, fmaf(w.w, h4.w, acc[r8]))));
            }
        }
#pragma unroll
        for (int r8 = 0; r8 < 8; r8++)
            hid[(rh * 8 + r8) * 128 + (tid & 127)] = fmaxf(acc[r8], 0.f);
    }
    __syncthreads();

    // ---- traj = hid @ W2^T + b2 ----
    for (int idx = tid; idx < 16 * 36; idx += 256) {
        int r = idx / 36, o = idx % 36;
        float a = b2[o];
        for (int k4 = 0; k4 < 32; k4++) {
            float4 w  = *(const float4*)&W2[(size_t)o * 128 + k4 * 4];
            float4 h4 = *(const float4*)&hid[r * 128 + k4 * 4];
            a = fmaf(w.x, h4.x, fmaf(w.y, h4.y, fmaf(w.z, h4.z, fmaf(w.w, h4.w, a))));
        }
        out[(size_t)(b0 + r) * 36 + o] = a;
    }
    // ---- probs: softmax over K=3 ----
    if (tid < 48) {
        int r = tid / 3, kk = tid % 3;
        float a = bp[kk];
        for (int k4 = 0; k4 < 64; k4++) {
            float4 w  = *(const float4*)&Wp[(size_t)kk * 256 + k4 * 4];
            float4 h4 = *(const float4*)&hf[r * 256 + k4 * 4];
            a = fmaf(w.x, h4.x, fmaf(w.y, h4.y, fmaf(w.z, h4.z, fmaf(w.w, h4.w, a))));
        }
        lg[r * 4 + kk] = a;
    }
    __syncthreads();
    if (tid < 48) {
        int r = tid / 3, kk = tid % 3;
        float m  = fmaxf(lg[r * 4], fmaxf(lg[r * 4 + 1], lg[r * 4 + 2]));
        float e0 = expf(lg[r * 4] - m), e1 = expf(lg[r * 4 + 1] - m), e2 = expf(lg[r * 4 + 2] - m);
        float e  = (kk == 0) ? e0 : ((kk == 1) ? e1 : e2);
        out[(size_t)BATCH * 36 + (size_t)(b0 + r) * 3 + kk] = e / (e0 + e1 + e2);
    }
}

// ---------------- launch ----------------
extern "C" void kernel_launch(void* const* d_in, const int* in_sizes, int n_in,
                              void* d_out, int out_size) {
    const float* x    = (const float*)d_in[0];
    const float* nb   = (const float*)d_in[1];
    const int*   mask = (const int*)  d_in[2];
    const float* We   = (const float*)d_in[3];
    const float* be   = (const float*)d_in[4];
    const float* Wih  = (const float*)d_in[5];
    const float* Whh  = (const float*)d_in[6];
    const float* bih  = (const float*)d_in[7];
    const float* bhh  = (const float*)d_in[8];
    const float* W1   = (const float*)d_in[9];
    const float* b1   = (const float*)d_in[10];
    const float* W2   = (const float*)d_in[11];
    const float* b2   = (const float*)d_in[12];
    const float* Wp   = (const float*)d_in[13];
    const float* bp   = (const float*)d_in[14];
    float* out = (float*)d_out;

    cudaFuncSetAttribute(lstm_fused_kernel, cudaFuncAttributeMaxDynamicSharedMemorySize, SMEM_BYTES);
    cudaFuncSetAttribute(head_kernel, cudaFuncAttributeMaxDynamicSharedMemorySize, H_SMEM_BYTES);

    prep_kernel<<<(12 * 512 * 8 + 255) / 256, 256>>>(Wih, Whh, bih, bhh);
    append_kernel<<<(NSEQ + 255) / 256, 256>>>(mask);
    pad_kernel<<<(NSEQ + 255) / 256, 256>>>();

    lstm_fused_kernel<<<NSEQ / MTILE, 512, SMEM_BYTES>>>(x, nb, We, be);

    head_kernel<<<BATCH / 16, 256, H_SMEM_BYTES>>>(mask, W1, b1, W2, b2, Wp, bp, out);
}

// round 13
// speedup vs baseline: 1.2556x; 1.1184x over previous
#include <cuda_runtime.h>
#include <math.h>
#include <stdint.h>

#define BATCH 8192
#define NMAX  16
#define TSTEPS 4
#define DIN   4
#define DEMB  64
#define HID   128
#define G4    512
#define NSEQ  (BATCH*(1+NMAX))     // 139264 sequences
#define MTILE 64                   // sequences per CTA

// ---------------- scratch (device globals: allocation-free) ----------------
__device__ float    g_H[(size_t)NSEQ*HID];      // final hidden; masked entries stay 0
__device__ uint32_t g_Wbf[12*2*512*8];          // weights bf16 hi/lo, permuted
__device__ float    g_bsum[G4];
__device__ int      g_cnt;                      // number of active sequences
__device__ int      g_active[NSEQ];             // compacted active ids (padded with 0)

// ---------------- smem layout (4-byte words) — C removed (now in registers) ----------------
// A 12288 | B 16384 | stage 8448 | bias 512 | We 256 | be 64 | ids 64
#define A_OFF  0
#define B_OFF  12288
#define ST_OFF 12288                 // stage aliases B (B dead when stage written at t=3)
#define BS_OFF 28672
#define WE_OFF 29184
#define BE_OFF 29440
#define ID_OFF 29504
#define SMEM_WORDS 29568
#define SMEM_BYTES (SMEM_WORDS*4)   // 118272

__device__ __forceinline__ void cp16(void* sdst, const void* gsrc) {
    uint32_t sa = (uint32_t)__cvta_generic_to_shared(sdst);
    asm volatile("cp.async.cg.shared.global [%0], [%1], 16;" :: "r"(sa), "l"(gsrc));
}
#define CP_COMMIT() asm volatile("cp.async.commit_group;" ::: "memory")
#define CP_WAIT(N)  asm volatile("cp.async.wait_group %0;" :: "n"(N) : "memory")

__device__ __forceinline__ uint32_t pack_bf2(float v0, float v1) {
    uint32_t r;
    asm("cvt.rn.bf16x2.f32 %0, %1, %2;" : "=r"(r) : "f"(v1), "f"(v0));
    return r;
}
__device__ __forceinline__ void split2(float v0, float v1, uint32_t& h, uint32_t& l) {
    h = pack_bf2(v0, v1);
    float r0 = v0 - __uint_as_float(h << 16);
    float r1 = v1 - __uint_as_float(h & 0xFFFF0000u);
    l = pack_bf2(r0, r1);
}

// fast gates: __expf (MUFU.EX2) + __fdividef (MUFU.RCP); ~2e-7 rel err per activation
__device__ __forceinline__ float fsig(float x)  { return __fdividef(1.f, 1.f + __expf(-x)); }
__device__ __forceinline__ float ftanh(float x) { return __fdividef(2.f, 1.f + __expf(-2.f * x)) - 1.f; }

#define MMA_BF16(D, A0,A1,A2,A3, B0,B1)                                        \
    asm volatile(                                                              \
        "mma.sync.aligned.m16n8k16.row.col.f32.bf16.bf16.f32 "                 \
        "{%0,%1,%2,%3},{%4,%5,%6,%7},{%8,%9},{%0,%1,%2,%3};"                   \
        : "+f"((D)[0]), "+f"((D)[1]), "+f"((D)[2]), "+f"((D)[3])               \
        : "r"(A0), "r"(A1), "r"(A2), "r"(A3), "r"(B0), "r"(B1))

// ---------------- prep: split weights; resets g_cnt ----------------
__global__ void prep_kernel(const float* __restrict__ Wih, const float* __restrict__ Whh,
                            const float* __restrict__ bih, const float* __restrict__ bhh) {
    int i = blockIdx.x * 256 + threadIdx.x;
    if (i == 0) g_cnt = 0;
    if (i < 12 * 512 * 8) {
        int w = i & 7, n = (i >> 3) & 511, c = i >> 12;
        int pp = (w & 1) ? 4 + (w >> 1) : (w >> 1);
        int k = c * 16 + 2 * pp;
        float v0, v1;
        if (k < DEMB) { v0 = Wih[n * DEMB + k];        v1 = Wih[n * DEMB + k + 1]; }
        else          { v0 = Whh[n * HID + (k - 64)];  v1 = Whh[n * HID + (k - 63)]; }
        uint32_t h, l;
        split2(v0, v1, h, l);
        g_Wbf[(c * 2 + 0) * 4096 + n * 8 + w] = h;
        g_Wbf[(c * 2 + 1) * 4096 + n * 8 + w] = l;
    }
    if (i < G4) g_bsum[i] = bih[i] + bhh[i];
}

// ---------------- compaction ----------------
__global__ void append_kernel(const int* __restrict__ mask) {
    int i = blockIdx.x * 256 + threadIdx.x;
    bool act = false;
    if (i < NSEQ) act = (i < BATCH) || (mask[i - BATCH] != 0);
    unsigned bal = __ballot_sync(0xFFFFFFFFu, act);
    int lane = threadIdx.x & 31;
    int n = __popc(bal);
    int base = 0;
    if (lane == 0 && n) base = atomicAdd(&g_cnt, n);
    base = __shfl_sync(0xFFFFFFFFu, base, 0);
    if (act) g_active[base + __popc(bal & ((1u << lane) - 1))] = i;
}

__global__ void pad_kernel() {
    int i = blockIdx.x * 256 + threadIdx.x;
    if (i < NSEQ && i >= g_cnt) g_active[i] = 0;   // duplicate seq 0: benign idempotent work
}

// ---------------- persistent 3xBF16 LSTM: C in registers, fast gates ----------------
__global__ void __launch_bounds__(512, 1)
lstm_fused_kernel(const float* __restrict__ x, const float* __restrict__ nb,
                  const float* __restrict__ We, const float* __restrict__ be) {
    if (blockIdx.x * MTILE >= g_cnt) return;       // fully-inactive CTA

    extern __shared__ uint32_t smw[];
    uint32_t* Asw = smw + A_OFF;
    uint32_t* Bsw = smw + B_OFF;
    float*    bs  = (float*)(smw + BS_OFF);
    float*    WeS = (float*)(smw + WE_OFF);
    float*    beS = (float*)(smw + BE_OFF);
    int*      ids = (int*)  (smw + ID_OFF);

    const int tid  = threadIdx.x;
    const int lane = tid & 31, wid = tid >> 5;
    const int wm = wid & 3, wn = wid >> 2;
    const int g = lane >> 2, q = lane & 3;
    const int m0 = wm * 16;
    const int row0 = blockIdx.x * MTILE;

    bs[tid] = g_bsum[tid];
    if (tid < 256) WeS[tid] = We[tid];
    if (tid < 64)  { beS[tid] = be[tid]; ids[tid] = g_active[row0 + tid]; }
    __syncthreads();

    auto compute_E = [&](int t) {
        const int row = tid >> 3, sub = tid & 7;
        const int id  = ids[row];
        const float* src = (id < BATCH)
            ? x  + ((size_t)id * TSTEPS + t) * DIN
            : nb + ((size_t)(id - BATCH) * TSTEPS + t) * DIN;
        float4 xv = *(const float4*)src;
#pragma unroll
        for (int ch = 0; ch < 4; ch++) {
            const int w  = sub;
            const int pp = (w & 1) ? 4 + (w >> 1) : (w >> 1);
            const int j  = ch * 16 + 2 * pp;
            float v0 = beS[j], v1 = beS[j + 1];
            v0 = fmaf(xv.x, WeS[j*4+0], v0); v0 = fmaf(xv.y, WeS[j*4+1], v0);
            v0 = fmaf(xv.z, WeS[j*4+2], v0); v0 = fmaf(xv.w, WeS[j*4+3], v0);
            v1 = fmaf(xv.x, WeS[(j+1)*4+0], v1); v1 = fmaf(xv.y, WeS[(j+1)*4+1], v1);
            v1 = fmaf(xv.z, WeS[(j+1)*4+2], v1); v1 = fmaf(xv.w, WeS[(j+1)*4+3], v1);
            v0 = fmaxf(v0, 0.f); v1 = fmaxf(v1, 0.f);
            uint32_t h, l;
            split2(v0, v1, h, l);
            Asw[(ch * 2 + 0) * 512 + row * 8 + w] = h;
            Asw[(ch * 2 + 1) * 512 + row * 8 + w] = l;
        }
    };
    auto load_B = [&](int c, int buf) {
#pragma unroll
        for (int i = 0; i < 4; i++) {
            int idx = tid + i * 512;
            cp16(Bsw + buf * 8192 + idx * 4, g_Wbf + c * 8192 + idx * 4);
        }
    };

    // cell state lives in registers: creg[s][h2*2+e], owned by this thread for all t
    float creg[4][4];
#pragma unroll
    for (int s = 0; s < 4; s++)
#pragma unroll
        for (int ci = 0; ci < 4; ci++) creg[s][ci] = 0.f;

    compute_E(0);
    load_B(0, 0); CP_COMMIT();
    load_B(1, 1); CP_COMMIT();

    for (int t = 0; t < TSTEPS; t++) {
        const int nch = (t == 0) ? 4 : 12;
        float acc[4][4][4];
#pragma unroll
        for (int a = 0; a < 4; a++)
#pragma unroll
            for (int b = 0; b < 4; b++)
#pragma unroll
                for (int c = 0; c < 4; c++) acc[a][b][c] = 0.f;

        for (int c = 0; c < nch; c++) {
            if (c == nch - 1) { CP_WAIT(0); } else { CP_WAIT(1); }
            __syncthreads();

            const uint32_t* Ach = Asw + (c * 2) * 512;
            uint2 ahA = *(const uint2*)(Ach + (m0 + g) * 8 + 2 * q);
            uint2 ahB = *(const uint2*)(Ach + (m0 + g + 8) * 8 + 2 * q);
            uint2 alA = *(const uint2*)(Ach + 512 + (m0 + g) * 8 + 2 * q);
            uint2 alB = *(const uint2*)(Ach + 512 + (m0 + g + 8) * 8 + 2 * q);
            const uint32_t* Bh = Bsw + (c & 1) * 8192;
            const uint32_t* Bl = Bh + 4096;
#pragma unroll
            for (int gate = 0; gate < 4; gate++)
#pragma unroll
                for (int s = 0; s < 4; s++) {
                    int n = gate * 128 + wn * 32 + s * 8 + g;
                    uint2 bh = *(const uint2*)(Bh + n * 8 + 2 * q);
                    uint2 bl = *(const uint2*)(Bl + n * 8 + 2 * q);
                    float* d = acc[gate][s];
                    MMA_BF16(d, ahA.x, ahB.x, ahA.y, ahB.y, bh.x, bh.y);
                    MMA_BF16(d, alA.x, alB.x, alA.y, alB.y, bh.x, bh.y);
                    MMA_BF16(d, ahA.x, ahB.x, ahA.y, ahB.y, bl.x, bl.y);
                }
            __syncthreads();

            // ---- prefetch / E-compute schedule (race-free; validated rounds 6-12) ----
            if (c + 2 < nch)                          { load_B(c + 2, c & 1); CP_COMMIT(); }
            else if (c == nch - 2 && t >= 1 && t < 3) { compute_E(t + 1); }
            else if (c == nch - 1 && t < 3) {
                if (t == 0) compute_E(1);
                load_B(0, 0); CP_COMMIT();
                load_B(1, 1); CP_COMMIT();
            }
        }

        // ---- register epilogue (fast gates, C in registers) ----
#pragma unroll
        for (int s = 0; s < 4; s++)
#pragma unroll
            for (int h2 = 0; h2 < 2; h2++) {
                const int rl = m0 + g + h2 * 8;
                const int j0 = wn * 32 + s * 8 + 2 * q;
                float hh[2];
#pragma unroll
                for (int e = 0; e < 2; e++) {
                    const int j  = j0 + e;
                    const int ci = h2 * 2 + e;
                    float iv = fsig (acc[0][s][ci] + bs[j]);
                    float fv = fsig (acc[1][s][ci] + bs[128 + j]);
                    float gv = ftanh(acc[2][s][ci] + bs[256 + j]);
                    float ov = fsig (acc[3][s][ci] + bs[384 + j]);
                    float cc = fmaf(fv, creg[s][ci], iv * gv);
                    creg[s][ci] = cc;
                    hh[e] = ov * ftanh(cc);
                }
                if (t < 3) {
                    const int ch = 4 + (j0 >> 4);
                    const int lp = (j0 & 15) >> 1;
                    const int w  = (lp < 4) ? 2 * lp : 2 * (lp - 4) + 1;
                    uint32_t h, l;
                    split2(hh[0], hh[1], h, l);
                    Asw[(ch * 2 + 0) * 512 + rl * 8 + w] = h;
                    Asw[(ch * 2 + 1) * 512 + rl * 8 + w] = l;
                } else {
                    float* stage = (float*)(smw + ST_OFF);   // aliases B (dead at t=3)
                    stage[rl * 132 + j0]     = hh[0];
                    stage[rl * 132 + j0 + 1] = hh[1];
                }
            }

        if (t == 3) {
            __syncthreads();
            const float* stage = (const float*)(smw + ST_OFF);
            const int r = tid >> 3, j0 = (tid & 7) * 16;
            const size_t hb = (size_t)ids[r] * HID;
#pragma unroll
            for (int v = 0; v < 4; v++) {
                float4 val = *(const float4*)&stage[r * 132 + j0 + v * 4];
                *(float4*)&g_H[hb + j0 + v * 4] = val;
            }
        }
    }
}

// ---------------- head v5 (round-12 verbatim) ----------------
#define H_HF   0
#define H_HID  4096
#define H_LG   6144
#define H_SMEM_FLOATS 6208
#define H_SMEM_BYTES (H_SMEM_FLOATS*4)

__global__ void __launch_bounds__(256) head_kernel(
        const int* __restrict__ mask,
        const float* __restrict__ W1, const float* __restrict__ b1,
        const float* __restrict__ W2, const float* __restrict__ b2,
        const float* __restrict__ Wp, const float* __restrict__ bp,
        float* __restrict__ out) {
    extern __shared__ float hs[];
    float* hf  = hs + H_HF;    // [16][256]
    float* hid = hs + H_HID;   // [16][128]
    float* lg  = hs + H_LG;    // [16][4]

    const int tid = threadIdx.x;
    const int b0  = blockIdx.x * 16;

    {
        const int r  = tid >> 4;
        const int j0 = (tid & 15) * 8;
        const int b  = b0 + r;
        float4 t0 = *(const float4*)&g_H[(size_t)b * HID + j0];
        float4 t1 = *(const float4*)&g_H[(size_t)b * HID + j0 + 4];
        *(float4*)&hf[r * 256 + j0]     = t0;
        *(float4*)&hf[r * 256 + j0 + 4] = t1;

        float4 sa = make_float4(0.f, 0.f, 0.f, 0.f);
        float4 sb = make_float4(0.f, 0.f, 0.f, 0.f);
        float cnt = 0.f;
#pragma unroll
        for (int n = 0; n < NMAX; n++) {
            float m = (float)mask[b * NMAX + n];
            const float* hp = &g_H[(size_t)(BATCH + b * NMAX + n) * HID + j0];
            float4 ha = *(const float4*)hp;
            float4 hb = *(const float4*)(hp + 4);
            sa.x = fmaf(m, ha.x, sa.x); sa.y = fmaf(m, ha.y, sa.y);
            sa.z = fmaf(m, ha.z, sa.z); sa.w = fmaf(m, ha.w, sa.w);
            sb.x = fmaf(m, hb.x, sb.x); sb.y = fmaf(m, hb.y, sb.y);
            sb.z = fmaf(m, hb.z, sb.z); sb.w = fmaf(m, hb.w, sb.w);
            cnt += m;
        }
        float cd = fmaxf(cnt, 1.f);
        hf[r * 256 + 128 + j0 + 0] = sa.x / cd;
        hf[r * 256 + 128 + j0 + 1] = sa.y / cd;
        hf[r * 256 + 128 + j0 + 2] = sa.z / cd;
        hf[r * 256 + 128 + j0 + 3] = sa.w / cd;
        hf[r * 256 + 128 + j0 + 4] = sb.x / cd;
        hf[r * 256 + 128 + j0 + 5] = sb.y / cd;
        hf[r * 256 + 128 + j0 + 6] = sb.z / cd;
        hf[r * 256 + 128 + j0 + 7] = sb.w / cd;
    }
    __syncthreads();

    {
        const int j = tid & 127, rh = tid >> 7;
        float acc[8];
        float bj = b1[j];
#pragma unroll
        for (int r = 0; r < 8; r++) acc[r] = bj;
        for (int k4 = 0; k4 < 64; k4++) {
            float4 w = *(const float4*)&W1[(size_t)j * 256 + k4 * 4];
#pragma unroll
            for (int r8 = 0; r8 < 8; r8++) {
                float4 h4 = *(const float4*)&hf[(rh * 8 + r8) * 256 + k4 * 4];
                acc[r8] = fmaf(w.x, h4.x, fmaf(w.y, h4.y, fmaf(w.z, h4.z, fmaf(w.w, h4.w, acc[r8]))));
            }
        }
#pragma unroll
        for (int r8 = 0; r8 < 8; r8++)
            hid[(rh * 8 + r8) * 128 + (tid & 127)] = fmaxf(acc[r8], 0.f);
    }
    __syncthreads();

    for (int idx = tid; idx < 16 * 36; idx += 256) {
        int r = idx / 36, o = idx % 36;
        float a = b2[o];
        for (int k4 = 0; k4 < 32; k4++) {
            float4 w  = *(const float4*)&W2[(size_t)o * 128 + k4 * 4];
            float4 h4 = *(const float4*)&hid[r * 128 + k4 * 4];
            a = fmaf(w.x, h4.x, fmaf(w.y, h4.y, fmaf(w.z, h4.z, fmaf(w.w, h4.w, a))));
        }
        out[(size_t)(b0 + r) * 36 + o] = a;
    }
    if (tid < 48) {
        int r = tid / 3, kk = tid % 3;
        float a = bp[kk];
        for (int k4 = 0; k4 < 64; k4++) {
            float4 w  = *(const float4*)&Wp[(size_t)kk * 256 + k4 * 4];
            float4 h4 = *(const float4*)&hf[r * 256 + k4 * 4];
            a = fmaf(w.x, h4.x, fmaf(w.y, h4.y, fmaf(w.z, h4.z, fmaf(w.w, h4.w, a))));
        }
        lg[r * 4 + kk] = a;
    }
    __syncthreads();
    if (tid < 48) {
        int r = tid / 3, kk = tid % 3;
        float m  = fmaxf(lg[r * 4], fmaxf(lg[r * 4 + 1], lg[r * 4 + 2]));
        float e0 = expf(lg[r * 4] - m), e1 = expf(lg[r * 4 + 1] - m), e2 = expf(lg[r * 4 + 2] - m);
        float e  = (kk == 0) ? e0 : ((kk == 1) ? e1 : e2);
        out[(size_t)BATCH * 36 + (size_t)(b0 + r) * 3 + kk] = e / (e0 + e1 + e2);
    }
}

// ---------------- launch ----------------
extern "C" void kernel_launch(void* const* d_in, const int* in_sizes, int n_in,
                              void* d_out, int out_size) {
    const float* x    = (const float*)d_in[0];
    const float* nb   = (const float*)d_in[1];
    const int*   mask = (const int*)  d_in[2];
    const float* We   = (const float*)d_in[3];
    const float* be   = (const float*)d_in[4];
    const float* Wih  = (const float*)d_in[5];
    const float* Whh  = (const float*)d_in[6];
    const float* bih  = (const float*)d_in[7];
    const float* bhh  = (const float*)d_in[8];
    const float* W1   = (const float*)d_in[9];
    const float* b1   = (const float*)d_in[10];
    const float* W2   = (const float*)d_in[11];
    const float* b2   = (const float*)d_in[12];
    const float* Wp   = (const float*)d_in[13];
    const float* bp   = (const float*)d_in[14];
    float* out = (float*)d_out;

    cudaFuncSetAttribute(lstm_fused_kernel, cudaFuncAttributeMaxDynamicSharedMemorySize, SMEM_BYTES);
    cudaFuncSetAttribute(head_kernel, cudaFuncAttributeMaxDynamicSharedMemorySize, H_SMEM_BYTES);

    prep_kernel<<<(12 * 512 * 8 + 255) / 256, 256>>>(Wih, Whh, bih, bhh);
    append_kernel<<<(NSEQ + 255) / 256, 256>>>(mask);
    pad_kernel<<<(NSEQ + 255) / 256, 256>>>();

    lstm_fused_kernel<<<NSEQ / MTILE, 512, SMEM_BYTES>>>(x, nb, We, be);

    head_kernel<<<BATCH / 16, 256, H_SMEM_BYTES>>>(mask, W1, b1, W2, b2, Wp, bp, out);
}

// round 14
// speedup vs baseline: 1.2642x; 1.0068x over previous
#include <cuda_runtime.h>
#include <math.h>
#include <stdint.h>

#define BATCH 8192
#define NMAX  16
#define TSTEPS 4
#define DIN   4
#define DEMB  64
#define HID   128
#define G4    512
#define NSEQ  (BATCH*(1+NMAX))     // 139264 sequences
#define MTILE 64                   // sequences per CTA

// ---------------- scratch (device globals: allocation-free) ----------------
__device__ float    g_H[(size_t)NSEQ*HID];      // final hidden; masked entries stay 0
// weights bf16 hi/lo INTERLEAVED: [chunk(12)][n(512)][16 words]
// words 4q+0,4q+1 = hi pairs (k 2q / 2q+8 perm), 4q+2,4q+3 = lo pairs
__device__ uint32_t g_Wbf[12*512*16];
__device__ float    g_bsum[G4];
__device__ int      g_cnt;
__device__ int      g_active[NSEQ];

// ---------------- smem layout (4-byte words) ----------------
// A: 12 chunks x 64 rows x 16 words (hi/lo interleaved) = 12288
// B: 2 bufs x 8192 = 16384 | stage aliases B | bias 512 | We 256 | be 64 | ids 64
#define A_OFF  0
#define B_OFF  12288
#define ST_OFF 12288
#define BS_OFF 28672
#define WE_OFF 29184
#define BE_OFF 29440
#define ID_OFF 29504
#define SMEM_WORDS 29568
#define SMEM_BYTES (SMEM_WORDS*4)   // 118272

__device__ __forceinline__ void cp16(void* sdst, const void* gsrc) {
    uint32_t sa = (uint32_t)__cvta_generic_to_shared(sdst);
    asm volatile("cp.async.cg.shared.global [%0], [%1], 16;" :: "r"(sa), "l"(gsrc));
}
#define CP_COMMIT() asm volatile("cp.async.commit_group;" ::: "memory")
#define CP_WAIT(N)  asm volatile("cp.async.wait_group %0;" :: "n"(N) : "memory")

__device__ __forceinline__ uint32_t pack_bf2(float v0, float v1) {
    uint32_t r;
    asm("cvt.rn.bf16x2.f32 %0, %1, %2;" : "=r"(r) : "f"(v1), "f"(v0));
    return r;
}
__device__ __forceinline__ void split2(float v0, float v1, uint32_t& h, uint32_t& l) {
    h = pack_bf2(v0, v1);
    float r0 = v0 - __uint_as_float(h << 16);
    float r1 = v1 - __uint_as_float(h & 0xFFFF0000u);
    l = pack_bf2(r0, r1);
}

__device__ __forceinline__ float fsig(float x)  { return __fdividef(1.f, 1.f + __expf(-x)); }
__device__ __forceinline__ float ftanh(float x) { return __fdividef(2.f, 1.f + __expf(-2.f * x)) - 1.f; }

#define MMA_BF16(D, A0,A1,A2,A3, B0,B1)                                        \
    asm volatile(                                                              \
        "mma.sync.aligned.m16n8k16.row.col.f32.bf16.bf16.f32 "                 \
        "{%0,%1,%2,%3},{%4,%5,%6,%7},{%8,%9},{%0,%1,%2,%3};"                   \
        : "+f"((D)[0]), "+f"((D)[1]), "+f"((D)[2]), "+f"((D)[3])               \
        : "r"(A0), "r"(A1), "r"(A2), "r"(A3), "r"(B0), "r"(B1))

// ---------------- prep: split weights to interleaved hi/lo; resets g_cnt ----------------
__global__ void prep_kernel(const float* __restrict__ Wih, const float* __restrict__ Whh,
                            const float* __restrict__ bih, const float* __restrict__ bhh) {
    int i = blockIdx.x * 256 + threadIdx.x;
    if (i == 0) g_cnt = 0;
    if (i < 12 * 512 * 8) {
        int w = i & 7, n = (i >> 3) & 511, c = i >> 12;
        int pp = (w & 1) ? 4 + (w >> 1) : (w >> 1);
        int k = c * 16 + 2 * pp;
        float v0, v1;
        if (k < DEMB) { v0 = Wih[n * DEMB + k];        v1 = Wih[n * DEMB + k + 1]; }
        else          { v0 = Whh[n * HID + (k - 64)];  v1 = Whh[n * HID + (k - 63)]; }
        uint32_t h, l;
        split2(v0, v1, h, l);
        int pos = 4 * (w >> 1) + (w & 1);               // interleave: hi at pos, lo at pos+2
        g_Wbf[c * 8192 + n * 16 + pos]     = h;
        g_Wbf[c * 8192 + n * 16 + pos + 2] = l;
    }
    if (i < G4) g_bsum[i] = bih[i] + bhh[i];
}

// ---------------- compaction ----------------
__global__ void append_kernel(const int* __restrict__ mask) {
    int i = blockIdx.x * 256 + threadIdx.x;
    bool act = false;
    if (i < NSEQ) act = (i < BATCH) || (mask[i - BATCH] != 0);
    unsigned bal = __ballot_sync(0xFFFFFFFFu, act);
    int lane = threadIdx.x & 31;
    int n = __popc(bal);
    int base = 0;
    if (lane == 0 && n) base = atomicAdd(&g_cnt, n);
    base = __shfl_sync(0xFFFFFFFFu, base, 0);
    if (act) g_active[base + __popc(bal & ((1u << lane) - 1))] = i;
}

__global__ void pad_kernel() {
    int i = blockIdx.x * 256 + threadIdx.x;
    if (i < NSEQ && i >= g_cnt) g_active[i] = 0;
}

// ---------------- persistent 3xBF16 LSTM: LDS.128 fragments, C in regs, fast gates ----------------
__global__ void __launch_bounds__(512, 1)
lstm_fused_kernel(const float* __restrict__ x, const float* __restrict__ nb,
                  const float* __restrict__ We, const float* __restrict__ be) {
    if (blockIdx.x * MTILE >= g_cnt) return;

    extern __shared__ uint32_t smw[];
    uint32_t* Asw = smw + A_OFF;
    uint32_t* Bsw = smw + B_OFF;
    float*    bs  = (float*)(smw + BS_OFF);
    float*    WeS = (float*)(smw + WE_OFF);
    float*    beS = (float*)(smw + BE_OFF);
    int*      ids = (int*)  (smw + ID_OFF);

    const int tid  = threadIdx.x;
    const int lane = tid & 31, wid = tid >> 5;
    const int wm = wid & 3, wn = wid >> 2;
    const int g = lane >> 2, q = lane & 3;
    const int m0 = wm * 16;
    const int row0 = blockIdx.x * MTILE;

    bs[tid] = g_bsum[tid];
    if (tid < 256) WeS[tid] = We[tid];
    if (tid < 64)  { beS[tid] = be[tid]; ids[tid] = g_active[row0 + tid]; }
    __syncthreads();

    auto compute_E = [&](int t) {
        const int row = tid >> 3, sub = tid & 7;
        const int id  = ids[row];
        const float* src = (id < BATCH)
            ? x  + ((size_t)id * TSTEPS + t) * DIN
            : nb + ((size_t)(id - BATCH) * TSTEPS + t) * DIN;
        float4 xv = *(const float4*)src;
#pragma unroll
        for (int ch = 0; ch < 4; ch++) {
            const int w  = sub;
            const int pp = (w & 1) ? 4 + (w >> 1) : (w >> 1);
            const int j  = ch * 16 + 2 * pp;
            float v0 = beS[j], v1 = beS[j + 1];
            v0 = fmaf(xv.x, WeS[j*4+0], v0); v0 = fmaf(xv.y, WeS[j*4+1], v0);
            v0 = fmaf(xv.z, WeS[j*4+2], v0); v0 = fmaf(xv.w, WeS[j*4+3], v0);
            v1 = fmaf(xv.x, WeS[(j+1)*4+0], v1); v1 = fmaf(xv.y, WeS[(j+1)*4+1], v1);
            v1 = fmaf(xv.z, WeS[(j+1)*4+2], v1); v1 = fmaf(xv.w, WeS[(j+1)*4+3], v1);
            v0 = fmaxf(v0, 0.f); v1 = fmaxf(v1, 0.f);
            uint32_t h, l;
            split2(v0, v1, h, l);
            int pos = 4 * (w >> 1) + (w & 1);
            Asw[ch * 1024 + row * 16 + pos]     = h;
            Asw[ch * 1024 + row * 16 + pos + 2] = l;
        }
    };
    auto load_B = [&](int c, int buf) {
#pragma unroll
        for (int i = 0; i < 4; i++) {
            int idx = tid + i * 512;
            cp16(Bsw + buf * 8192 + idx * 4, g_Wbf + c * 8192 + idx * 4);
        }
    };

    float creg[4][4];
#pragma unroll
    for (int s = 0; s < 4; s++)
#pragma unroll
        for (int ci = 0; ci < 4; ci++) creg[s][ci] = 0.f;

    compute_E(0);
    load_B(0, 0); CP_COMMIT();
    load_B(1, 1); CP_COMMIT();

    for (int t = 0; t < TSTEPS; t++) {
        const int nch = (t == 0) ? 4 : 12;
        float acc[4][4][4];
#pragma unroll
        for (int a = 0; a < 4; a++)
#pragma unroll
            for (int b = 0; b < 4; b++)
#pragma unroll
                for (int c = 0; c < 4; c++) acc[a][b][c] = 0.f;

        for (int c = 0; c < nch; c++) {
            if (c == nch - 1) { CP_WAIT(0); } else { CP_WAIT(1); }
            __syncthreads();

            // ---- fragment loads: one LDS.128 each (hi pair + lo pair together) ----
            const uint32_t* Ach = Asw + c * 1024;
            uint4 aA = *(const uint4*)(Ach + (m0 + g) * 16 + 4 * q);      // x,y=hi  z,w=lo
            uint4 aB = *(const uint4*)(Ach + (m0 + g + 8) * 16 + 4 * q);
            const uint32_t* Bc = Bsw + (c & 1) * 8192;
#pragma unroll
            for (int gate = 0; gate < 4; gate++)
#pragma unroll
                for (int s = 0; s < 4; s++) {
                    int n = gate * 128 + wn * 32 + s * 8 + g;
                    uint4 bv = *(const uint4*)(Bc + n * 16 + 4 * q);      // x,y=hi z,w=lo
                    float* d = acc[gate][s];
                    MMA_BF16(d, aA.x, aB.x, aA.y, aB.y, bv.x, bv.y);      // hi*hi
                    MMA_BF16(d, aA.z, aB.z, aA.w, aB.w, bv.x, bv.y);      // lo*hi
                    MMA_BF16(d, aA.x, aB.x, aA.y, aB.y, bv.z, bv.w);      // hi*lo
                }
            __syncthreads();

            // ---- prefetch / E-compute schedule (race-free; validated rounds 6-13) ----
            if (c + 2 < nch)                          { load_B(c + 2, c & 1); CP_COMMIT(); }
            else if (c == nch - 2 && t >= 1 && t < 3) { compute_E(t + 1); }
            else if (c == nch - 1 && t < 3) {
                if (t == 0) compute_E(1);
                load_B(0, 0); CP_COMMIT();
                load_B(1, 1); CP_COMMIT();
            }
        }

        // ---- register epilogue (fast gates, C in registers) ----
#pragma unroll
        for (int s = 0; s < 4; s++)
#pragma unroll
            for (int h2 = 0; h2 < 2; h2++) {
                const int rl = m0 + g + h2 * 8;
                const int j0 = wn * 32 + s * 8 + 2 * q;
                float hh[2];
#pragma unroll
                for (int e = 0; e < 2; e++) {
                    const int j  = j0 + e;
                    const int ci = h2 * 2 + e;
                    float iv = fsig (acc[0][s][ci] + bs[j]);
                    float fv = fsig (acc[1][s][ci] + bs[128 + j]);
                    float gv = ftanh(acc[2][s][ci] + bs[256 + j]);
                    float ov = fsig (acc[3][s][ci] + bs[384 + j]);
                    float cc = fmaf(fv, creg[s][ci], iv * gv);
                    creg[s][ci] = cc;
                    hh[e] = ov * ftanh(cc);
                }
                if (t < 3) {
                    const int ch = 4 + (j0 >> 4);
                    const int lp = (j0 & 15) >> 1;
                    const int w  = (lp < 4) ? 2 * lp : 2 * (lp - 4) + 1;
                    uint32_t h, l;
                    split2(hh[0], hh[1], h, l);
                    int pos = 4 * (w >> 1) + (w & 1);
                    Asw[ch * 1024 + rl * 16 + pos]     = h;
                    Asw[ch * 1024 + rl * 16 + pos + 2] = l;
                } else {
                    float* stage = (float*)(smw + ST_OFF);
                    stage[rl * 132 + j0]     = hh[0];
                    stage[rl * 132 + j0 + 1] = hh[1];
                }
            }

        if (t == 3) {
            __syncthreads();
            const float* stage = (const float*)(smw + ST_OFF);
            const int r = tid >> 3, j0 = (tid & 7) * 16;
            const size_t hb = (size_t)ids[r] * HID;
#pragma unroll
            for (int v = 0; v < 4; v++) {
                float4 val = *(const float4*)&stage[r * 132 + j0 + v * 4];
                *(float4*)&g_H[hb + j0 + v * 4] = val;
            }
        }
    }
}

// ---------------- head v5 (round-12/13 verbatim) ----------------
#define H_HF   0
#define H_HID  4096
#define H_LG   6144
#define H_SMEM_FLOATS 6208
#define H_SMEM_BYTES (H_SMEM_FLOATS*4)

__global__ void __launch_bounds__(256) head_kernel(
        const int* __restrict__ mask,
        const float* __restrict__ W1, const float* __restrict__ b1,
        const float* __restrict__ W2, const float* __restrict__ b2,
        const float* __restrict__ Wp, const float* __restrict__ bp,
        float* __restrict__ out) {
    extern __shared__ float hs[];
    float* hf  = hs + H_HF;
    float* hid = hs + H_HID;
    float* lg  = hs + H_LG;

    const int tid = threadIdx.x;
    const int b0  = blockIdx.x * 16;

    {
        const int r  = tid >> 4;
        const int j0 = (tid & 15) * 8;
        const int b  = b0 + r;
        float4 t0 = *(const float4*)&g_H[(size_t)b * HID + j0];
        float4 t1 = *(const float4*)&g_H[(size_t)b * HID + j0 + 4];
        *(float4*)&hf[r * 256 + j0]     = t0;
        *(float4*)&hf[r * 256 + j0 + 4] = t1;

        float4 sa = make_float4(0.f, 0.f, 0.f, 0.f);
        float4 sb = make_float4(0.f, 0.f, 0.f, 0.f);
        float cnt = 0.f;
#pragma unroll
        for (int n = 0; n < NMAX; n++) {
            float m = (float)mask[b * NMAX + n];
            const float* hp = &g_H[(size_t)(BATCH + b * NMAX + n) * HID + j0];
            float4 ha = *(const float4*)hp;
            float4 hb = *(const float4*)(hp + 4);
            sa.x = fmaf(m, ha.x, sa.x); sa.y = fmaf(m, ha.y, sa.y);
            sa.z = fmaf(m, ha.z, sa.z); sa.w = fmaf(m, ha.w, sa.w);
            sb.x = fmaf(m, hb.x, sb.x); sb.y = fmaf(m, hb.y, sb.y);
            sb.z = fmaf(m, hb.z, sb.z); sb.w = fmaf(m, hb.w, sb.w);
            cnt += m;
        }
        float cd = fmaxf(cnt, 1.f);
        hf[r * 256 + 128 + j0 + 0] = sa.x / cd;
        hf[r * 256 + 128 + j0 + 1] = sa.y / cd;
        hf[r * 256 + 128 + j0 + 2] = sa.z / cd;
        hf[r * 256 + 128 + j0 + 3] = sa.w / cd;
        hf[r * 256 + 128 + j0 + 4] = sb.x / cd;
        hf[r * 256 + 128 + j0 + 5] = sb.y / cd;
        hf[r * 256 + 128 + j0 + 6] = sb.z / cd;
        hf[r * 256 + 128 + j0 + 7] = sb.w / cd;
    }
    __syncthreads();

    {
        const int j = tid & 127, rh = tid >> 7;
        float acc[8];
        float bj = b1[j];
#pragma unroll
        for (int r = 0; r < 8; r++) acc[r] = bj;
        for (int k4 = 0; k4 < 64; k4++) {
            float4 w = *(const float4*)&W1[(size_t)j * 256 + k4 * 4];
#pragma unroll
            for (int r8 = 0; r8 < 8; r8++) {
                float4 h4 = *(const float4*)&hf[(rh * 8 + r8) * 256 + k4 * 4];
                acc[r8] = fmaf(w.x, h4.x, fmaf(w.y, h4.y, fmaf(w.z, h4.z, fmaf(w.w, h4.w, acc[r8]))));
            }
        }
#pragma unroll
        for (int r8 = 0; r8 < 8; r8++)
            hid[(rh * 8 + r8) * 128 + (tid & 127)] = fmaxf(acc[r8], 0.f);
    }
    __syncthreads();

    for (int idx = tid; idx < 16 * 36; idx += 256) {
        int r = idx / 36, o = idx % 36;
        float a = b2[o];
        for (int k4 = 0; k4 < 32; k4++) {
            float4 w  = *(const float4*)&W2[(size_t)o * 128 + k4 * 4];
            float4 h4 = *(const float4*)&hid[r * 128 + k4 * 4];
            a = fmaf(w.x, h4.x, fmaf(w.y, h4.y, fmaf(w.z, h4.z, fmaf(w.w, h4.w, a))));
        }
        out[(size_t)(b0 + r) * 36 + o] = a;
    }
    if (tid < 48) {
        int r = tid / 3, kk = tid % 3;
        float a = bp[kk];
        for (int k4 = 0; k4 < 64; k4++) {
            float4 w  = *(const float4*)&Wp[(size_t)kk * 256 + k4 * 4];
            float4 h4 = *(const float4*)&hf[r * 256 + k4 * 4];
            a = fmaf(w.x, h4.x, fmaf(w.y, h4.y, fmaf(w.z, h4.z, fmaf(w.w, h4.w, a))));
        }
        lg[r * 4 + kk] = a;
    }
    __syncthreads();
    if (tid < 48) {
        int r = tid / 3, kk = tid % 3;
        float m  = fmaxf(lg[r * 4], fmaxf(lg[r * 4 + 1], lg[r * 4 + 2]));
        float e0 = expf(lg[r * 4] - m), e1 = expf(lg[r * 4 + 1] - m), e2 = expf(lg[r * 4 + 2] - m);
        float e  = (kk == 0) ? e0 : ((kk == 1) ? e1 : e2);
        out[(size_t)BATCH * 36 + (size_t)(b0 + r) * 3 + kk] = e / (e0 + e1 + e2);
    }
}

// ---------------- launch ----------------
extern "C" void kernel_launch(void* const* d_in, const int* in_sizes, int n_in,
                              void* d_out, int out_size) {
    const float* x    = (const float*)d_in[0];
    const float* nb   = (const float*)d_in[1];
    const int*   mask = (const int*)  d_in[2];
    const float* We   = (const float*)d_in[3];
    const float* be   = (const float*)d_in[4];
    const float* Wih  = (const float*)d_in[5];
    const float* Whh  = (const float*)d_in[6];
    const float* bih  = (const float*)d_in[7];
    const float* bhh  = (const float*)d_in[8];
    const float* W1   = (const float*)d_in[9];
    const float* b1   = (const float*)d_in[10];
    const float* W2   = (const float*)d_in[11];
    const float* b2   = (const float*)d_in[12];
    const float* Wp   = (const float*)d_in[13];
    const float* bp   = (const float*)d_in[14];
    float* out = (float*)d_out;

    cudaFuncSetAttribute(lstm_fused_kernel, cudaFuncAttributeMaxDynamicSharedMemorySize, SMEM_BYTES);
    cudaFuncSetAttribute(head_kernel, cudaFuncAttributeMaxDynamicSharedMemorySize, H_SMEM_BYTES);

    prep_kernel<<<(12 * 512 * 8 + 255) / 256, 256>>>(Wih, Whh, bih, bhh);
    append_kernel<<<(NSEQ + 255) / 256, 256>>>(mask);
    pad_kernel<<<(NSEQ + 255) / 256, 256>>>();

    lstm_fused_kernel<<<NSEQ / MTILE, 512, SMEM_BYTES>>>(x, nb, We, be);

    head_kernel<<<BATCH / 16, 256, H_SMEM_BYTES>>>(mask, W1, b1, W2, b2, Wp, bp, out);
}